// round 13
// baseline (speedup 1.0000x reference)
#include <cuda_runtime.h>
#include <cuda_fp16.h>
#include <cstdint>

// ============================================================================
// x (64,112,112,64) f32 NHWC; kernels (3,3,64,64) f32 HWIO (+-1); beta (64).
// out = conv3x3_SAME(BN_train(x), kernels), fp32.
//
// BN folded into GEMM: out = conv(fp16(x_raw), w*s_ci) + bias_co; padded
// border = fp16(-shift/scale). Implicit GEMM mma.sync.m16n8k16.f16.
// Conv: persistent CTAs, 384 thr = 12 warps = 6 pairs (3 warps/SMSP).
// Pair shares a 32-pixel A buffer (double buffered, cp.async); warp tile
// 32 px x 32 co -> B smem bytes/MAC halved vs 16-px tiles (R12 ncu: L1=68%,
// tensor=37%, LDS+MMA additive => smem-traffic serialized; cut the bytes).
// ============================================================================

#define N_  64
#define H_  112
#define W_  112
#define C_  64
#define HP  114
#define WP  114
#define M_CNT (N_*H_*W_)
#define NVEC  ((size_t)M_CNT * 16)
#define NPIX  (N_*H_*W_)
#define HW_   (H_*W_)                // 12544
#define PIXB  (C_*2)                 // 128 B per padded pixel
#define ROWB  (WP*PIXB)              // 14592 B per padded row
#define SBLK  1024                   // stats blocks

#define CTATILE 192
#define NTILES2 ((NPIX + CTATILE - 1) / CTATILE)   // 4182 (last tile 64 px)

// B: [3 dy][192 k][64 co] fp16, 128B rows, XOR swizzle (k&7)<<4
#define BROWB  128
#define BCHUNKB (192*BROWB)          // 24576
#define B_BYTES (3*BCHUNKB)          // 73728

// A: per-PAIR [32 pixels][192 k] fp16, pitch 400B, double buffered
#define APITCH 400
#define AWBUF  (32*APITCH)           // 12800
#define SM_A0  B_BYTES
#define CONV_SMEM (B_BYTES + 6*2*AWBUF)   // 227328

// ---------------- persistent device scratch (zero-init .bss) ----------------
__device__ __align__(16) unsigned short g_xf[(size_t)N_ * HP * WP * C_];
__device__ __align__(16) unsigned short g_wb[3 * 192 * 64];
__device__ float g_psum[SBLK * C_];
__device__ float g_psq[SBLK * C_];
__device__ float g_scale[C_];
__device__ float g_shift[C_];
__device__ float g_bias[C_];
__device__ unsigned short g_bord[C_];

// ============================ PTX helpers ===================================
__device__ __forceinline__ uint32_t smem_to_u32(const void* p) {
    uint32_t a;
    asm("{ .reg .u64 t; cvta.to.shared.u64 t, %1; cvt.u32.u64 %0, t; }"
        : "=r"(a) : "l"(p));
    return a;
}

#define LDSM_X4(r, addr) \
    asm volatile("ldmatrix.sync.aligned.m8n8.x4.shared.b16 {%0,%1,%2,%3}, [%4];" \
        : "=r"((r)[0]), "=r"((r)[1]), "=r"((r)[2]), "=r"((r)[3]) : "r"(addr))

#define LDSM_X4_T(r, addr) \
    asm volatile("ldmatrix.sync.aligned.m8n8.x4.trans.shared.b16 {%0,%1,%2,%3}, [%4];" \
        : "=r"((r)[0]), "=r"((r)[1]), "=r"((r)[2]), "=r"((r)[3]) : "r"(addr))

#define MMA16816(c, a, b0v, b1v) \
    asm volatile("mma.sync.aligned.m16n8k16.row.col.f32.f16.f16.f32 " \
        "{%0,%1,%2,%3}, {%4,%5,%6,%7}, {%8,%9}, {%0,%1,%2,%3};" \
        : "+f"((c)[0]), "+f"((c)[1]), "+f"((c)[2]), "+f"((c)[3]) \
        : "r"((a)[0]), "r"((a)[1]), "r"((a)[2]), "r"((a)[3]), \
          "r"(b0v), "r"(b1v))

#define CP_ASYNC16(dst_s, src_g) \
    asm volatile("cp.async.cg.shared.global [%0], [%1], 16;" \
        :: "r"(dst_s), "l"(src_g))
#define CP_COMMIT() asm volatile("cp.async.commit_group;" ::: "memory")
#define CP_WAIT0()  asm volatile("cp.async.wait_group 0;" ::: "memory")
#define BAR_SYNC(id) asm volatile("bar.sync %0, 64;" :: "r"(id) : "memory")

__device__ __forceinline__ unsigned short f2h(float f) {
    __half h = __float2half_rn(f);
    return *reinterpret_cast<unsigned short*>(&h);
}

// ---------------------------------------------------------------------------
// Launch 0: per-channel partial moments (per-block) + raw-x fp16 conversion.
__global__ void __launch_bounds__(256) k_stats_conv(const float* __restrict__ x) {
    __shared__ float ssum[C_];
    __shared__ float ssq[C_];
    int tid = threadIdx.x;
    if (tid < C_) { ssum[tid] = 0.0f; ssq[tid] = 0.0f; }
    __syncthreads();

    const float4* xv = (const float4*)x;
    uint2* of = (uint2*)g_xf;
    int g = tid & 15;
    float4 s = make_float4(0.f, 0.f, 0.f, 0.f);
    float4 q = make_float4(0.f, 0.f, 0.f, 0.f);
    size_t stride = (size_t)gridDim.x * blockDim.x;
    for (size_t i = (size_t)blockIdx.x * blockDim.x + tid; i < NVEC; i += stride) {
        float4 v = xv[i];
        s.x += v.x; s.y += v.y; s.z += v.z; s.w += v.w;
        q.x += v.x * v.x; q.y += v.y * v.y; q.z += v.z * v.z; q.w += v.w * v.w;

        size_t pix = i >> 4;
        int n   = (int)(pix / HW_);
        int rem = (int)(pix % HW_);
        int h   = rem / W_;
        int w   = rem % W_;
        unsigned short h0 = f2h(v.x), h1 = f2h(v.y), h2 = f2h(v.z), h3 = f2h(v.w);
        size_t dpix = ((size_t)n * HP + (h + 1)) * WP + (w + 1);
        of[dpix * 16 + g] = make_uint2((uint32_t)h0 | ((uint32_t)h1 << 16),
                                       (uint32_t)h2 | ((uint32_t)h3 << 16));
    }
    atomicAdd(&ssum[g * 4 + 0], s.x); atomicAdd(&ssq[g * 4 + 0], q.x);
    atomicAdd(&ssum[g * 4 + 1], s.y); atomicAdd(&ssq[g * 4 + 1], q.y);
    atomicAdd(&ssum[g * 4 + 2], s.z); atomicAdd(&ssq[g * 4 + 2], q.z);
    atomicAdd(&ssum[g * 4 + 3], s.w); atomicAdd(&ssq[g * 4 + 3], q.w);
    __syncthreads();
    if (tid < C_) {
        g_psum[blockIdx.x * C_ + tid] = ssum[tid];
        g_psq [blockIdx.x * C_ + tid] = ssq[tid];
    }
}

// ---------------------------------------------------------------------------
// Launch 1: parallel reduce partials -> scale/shift/border + bias. 512 thr.
__global__ void __launch_bounds__(512) k_finprep(const float* __restrict__ beta,
                                                 const float* __restrict__ kw) {
    __shared__ float rs[C_ * 8];
    __shared__ float rq[C_ * 8];
    int tid = threadIdx.x;               // 512 = 64 channels x 8 slices
    int c = tid >> 3;
    int k = tid & 7;
    float s = 0.0f, q = 0.0f;
    for (int b = k; b < SBLK; b += 8) {
        s += g_psum[b * C_ + c];
        q += g_psq [b * C_ + c];
    }
    rs[tid] = s; rq[tid] = q;
    __syncthreads();
    if (tid < C_) {
        float ts = 0.0f, tq = 0.0f;
        #pragma unroll
        for (int i = 0; i < 8; i++) { ts += rs[tid * 8 + i]; tq += rq[tid * 8 + i]; }
        const float inv_m = 1.0f / (float)M_CNT;
        float m  = ts * inv_m;
        float v  = tq * inv_m - m * m;
        float sc = rsqrtf(v + 1e-5f);
        float sh = beta[tid] - m * sc;
        g_scale[tid] = sc;
        g_shift[tid] = sh;
        g_bord[tid]  = f2h(-sh / sc);
    }
    __syncthreads();
    {
        float acc = 0.0f;
        for (int t = k; t < 9; t += 8)
            for (int ci = 0; ci < 64; ci++)
                acc += kw[((size_t)t * 64 + ci) * 64 + c] * g_shift[ci];
        rs[tid] = acc;
    }
    __syncthreads();
    if (tid < C_) {
        float a = 0.0f;
        #pragma unroll
        for (int i = 0; i < 8; i++) a += rs[tid * 8 + i];
        g_bias[tid] = a;
    }
}

// ---------------------------------------------------------------------------
// Launch 2: swizzled B image + border fill.
__global__ void __launch_bounds__(256) k_bw(const float* __restrict__ kw) {
    int i = blockIdx.x * blockDim.x + threadIdx.x;
    if (i < 36864) {
        int cout = i & 63;
        int cin  = (i >> 6) & 63;
        int t    = i >> 12;            // dy*3+dx
        int dy = t / 3, dx = t % 3;
        float v = kw[((size_t)t * 64 + cin) * 64 + cout] * g_scale[cin];
        int kk = dx * 64 + cin;
        int off = kk * BROWB + cout * 2;
        off ^= (kk & 7) << 4;
        *(unsigned short*)((char*)g_wb + (size_t)dy * BCHUNKB + off) = f2h(v);
        return;
    }
    int idx = i - 36864;
    if (idx >= 64 * 452 * 16) return;
    int g   = idx & 15;
    int bp  = (idx >> 4) % 452;
    int img = (idx >> 4) / 452;
    int h, w;
    if (bp < 114)      { h = 0;   w = bp; }
    else if (bp < 228) { h = 113; w = bp - 114; }
    else { int j = bp - 228; h = 1 + (j >> 1); w = (j & 1) ? 113 : 0; }
    const unsigned short* bd = g_bord;
    uint32_t v0 = (uint32_t)bd[g*4+0] | ((uint32_t)bd[g*4+1] << 16);
    uint32_t v1 = (uint32_t)bd[g*4+2] | ((uint32_t)bd[g*4+3] << 16);
    ((uint2*)g_xf)[(((size_t)img * HP + h) * WP + w) * 16 + g] = make_uint2(v0, v1);
}

// ---------------------------------------------------------------------------
// Launch 3 (profiled): conv. 384 thr = 12 warps = 6 pairs; warp tile 32x32.
// CTA tile 192 px; last tile partial (loads clamped, stores predicated).
__global__ void __launch_bounds__(384, 1)
k_conv(float* __restrict__ out) {
    extern __shared__ __align__(1024) unsigned char smem[];
    uint32_t sb = smem_to_u32(smem);
    int tid = threadIdx.x;

    // stage B once (pre-swizzled image)
    {
        const uint4* src = (const uint4*)g_wb;
        uint4* dst = (uint4*)smem;
        for (int i = tid; i < B_BYTES / 16; i += 384) dst[i] = src[i];
    }
    __syncthreads();

    int lane = tid & 31;
    int wid  = tid >> 5;           // 0..11
    int pr   = wid >> 1;           // pair 0..5 -> pixels pr*32..+32
    int nw   = wid & 1;            // n-half: couts nw*32..+32
    int sel  = lane >> 3;
    int l7   = lane & 7;
    int barid = pr + 1;            // named barriers 1..6

    uint32_t apbase = sb + SM_A0 + (uint32_t)pr * (2 * AWBUF);
    uint32_t a_off  = (uint32_t)(((sel & 1) * 8 + l7) * APITCH + (sel >> 1) * 16);

    uint32_t b_lane = sb + (uint32_t)(((sel & 1) * 8 + l7) * BROWB);
    uint32_t bo0 = (uint32_t)((((sel >> 1) * 16) + nw * 64)      ^ (l7 << 4));
    uint32_t bo1 = (uint32_t)((((sel >> 1) * 16) + nw * 64 + 32) ^ (l7 << 4));

    // staging: 64 threads/pair; thread pt covers pixel pt>>1, half pt&1 (192B)
    int pt = tid & 63;
    uint32_t dst_off = (uint32_t)((pt >> 1) * APITCH + (pt & 1) * 192);
    uint32_t src_off = (uint32_t)((pt & 1) * 192);
    const char* gx = (const char*)g_xf;

    int cq = lane & 3;
    float bia0[4], bia1[4];
    #pragma unroll
    for (int nf = 0; nf < 4; nf++) {
        bia0[nf] = g_bias[nw * 32 + nf * 8 + 2 * cq];
        bia1[nf] = g_bias[nw * 32 + nf * 8 + 2 * cq + 1];
    }

    uint32_t jj = 0;

    // prologue: prefetch (first tile, dy=0) into buf 0
    {
        int gp  = blockIdx.x * CTATILE + pr * 32 + (pt >> 1);
        if (gp >= NPIX) gp = NPIX - 1;
        int n   = gp / HW_;
        int rem = gp % HW_;
        int h   = rem / W_;
        int w   = rem % W_;
        const char* src = gx + (((size_t)n * HP + h) * WP + w) * PIXB + src_off;
        uint32_t d = apbase + dst_off;
        #pragma unroll
        for (int i = 0; i < 12; i++) CP_ASYNC16(d + i * 16, src + i * 16);
        CP_COMMIT();
    }

    for (int tile = blockIdx.x; tile < NTILES2; tile += gridDim.x) {
        int gp  = tile * CTATILE + pr * 32 + (pt >> 1);
        if (gp >= NPIX) gp = NPIX - 1;
        int n   = gp / HW_;
        int rem = gp % HW_;
        int h   = rem / W_;
        int w   = rem % W_;
        const char* base = gx + (((size_t)n * HP + h) * WP + w) * PIXB + src_off;

        float c[32];
        #pragma unroll
        for (int i = 0; i < 32; i++) c[i] = 0.0f;

        #pragma unroll 1
        for (int j = 0; j < 3; j++) {
            uint32_t buf  = jj & 1;
            uint32_t nbuf = buf ^ 1;
            jj++;

            // 1) chunk data landed; 2) both warps of pair done reading nbuf
            CP_WAIT0();
            BAR_SYNC(barid);

            // 3) prefetch next chunk into nbuf (overlaps MMA loop below)
            if (j < 2) {
                const char* src = base + (size_t)(j + 1) * ROWB;
                uint32_t d = apbase + nbuf * AWBUF + dst_off;
                #pragma unroll
                for (int i = 0; i < 12; i++) CP_ASYNC16(d + i * 16, src + i * 16);
                CP_COMMIT();
            } else {
                int t2 = tile + gridDim.x;
                if (t2 < NTILES2) {
                    int gp2  = t2 * CTATILE + pr * 32 + (pt >> 1);
                    if (gp2 >= NPIX) gp2 = NPIX - 1;
                    int n2   = gp2 / HW_;
                    int rem2 = gp2 % HW_;
                    int h2   = rem2 / W_;
                    int w2   = rem2 % W_;
                    const char* src = gx + (((size_t)n2 * HP + h2) * WP + w2) * PIXB + src_off;
                    uint32_t d = apbase + nbuf * AWBUF + dst_off;
                    #pragma unroll
                    for (int i = 0; i < 12; i++) CP_ASYNC16(d + i * 16, src + i * 16);
                    CP_COMMIT();
                }
            }

            uint32_t Abase = apbase + buf * AWBUF + a_off;
            uint32_t Bbase = b_lane + (uint32_t)j * BCHUNKB;

            #pragma unroll
            for (int s = 0; s < 12; s++) {
                uint32_t ra0[4], ra1[4], rb0[4], rb1[4];
                LDSM_X4(ra0, Abase + s * 32);
                LDSM_X4(ra1, Abase + 16 * APITCH + s * 32);
                uint32_t Bs = Bbase + (uint32_t)s * (16 * BROWB);
                LDSM_X4_T(rb0, Bs + bo0);
                LDSM_X4_T(rb1, Bs + bo1);

                MMA16816(c +  0, ra0, rb0[0], rb0[1]);
                MMA16816(c +  4, ra0, rb0[2], rb0[3]);
                MMA16816(c +  8, ra0, rb1[0], rb1[1]);
                MMA16816(c + 12, ra0, rb1[2], rb1[3]);
                MMA16816(c + 16, ra1, rb0[0], rb0[1]);
                MMA16816(c + 20, ra1, rb0[2], rb0[3]);
                MMA16816(c + 24, ra1, rb1[0], rb1[1]);
                MMA16816(c + 28, ra1, rb1[2], rb1[3]);
            }
        }

        // epilogue: add bias, store 32 pixels x 32 couts (predicated for tail)
        int r = lane >> 2;
        #pragma unroll
        for (int mf = 0; mf < 2; mf++) {
            int pix0 = tile * CTATILE + pr * 32 + mf * 16 + r;
            float* p0 = out + (size_t)pix0 * 64 + nw * 32 + 2 * cq;
            float* p1 = p0 + 8 * 64;
            if (pix0 < NPIX) {
                #pragma unroll
                for (int nf = 0; nf < 4; nf++)
                    *(float2*)(p0 + nf * 8) = make_float2(c[mf*16 + nf*4 + 0] + bia0[nf],
                                                          c[mf*16 + nf*4 + 1] + bia1[nf]);
            }
            if (pix0 + 8 < NPIX) {
                #pragma unroll
                for (int nf = 0; nf < 4; nf++)
                    *(float2*)(p1 + nf * 8) = make_float2(c[mf*16 + nf*4 + 2] + bia0[nf],
                                                          c[mf*16 + nf*4 + 3] + bia1[nf]);
            }
        }
    }
}

// ---------------------------------------------------------------------------
extern "C" void kernel_launch(void* const* d_in, const int* in_sizes, int n_in,
                              void* d_out, int out_size) {
    const float* x    = (const float*)d_in[0];
    const float* kw   = (const float*)d_in[1];
    const float* beta = (const float*)d_in[2];
    float* out = (float*)d_out;
    (void)in_sizes; (void)n_in; (void)out_size;

    cudaFuncSetAttribute(k_conv, cudaFuncAttributeMaxDynamicSharedMemorySize, CONV_SMEM);

    k_stats_conv<<<SBLK, 256>>>(x);                              // launch 0
    k_finprep<<<1, 512>>>(beta, kw);                             // launch 1
    k_bw<<<(36864 + 64 * 452 * 16 + 255) / 256, 256>>>(kw);      // launch 2
    k_conv<<<152, 384, CONV_SMEM>>>(out);                        // launch 3 (profiled)
}

// round 14
// speedup vs baseline: 1.0301x; 1.0301x over previous
#include <cuda_runtime.h>
#include <cuda_fp16.h>
#include <cstdint>

// ============================================================================
// x (64,112,112,64) f32 NHWC; kernels (3,3,64,64) f32 HWIO (+-1); beta (64).
// out = conv3x3_SAME(BN_train(x), kernels), fp32.
//
// BN folded into GEMM: out = conv(fp16(x_raw), w*s_ci) + bias_co; padded
// border = fp16(-shift/scale). Implicit GEMM mma.sync.m16n8k16.f16.
// Conv: persistent CTAs, 512 thr = 16 warps = 8 pairs; warp tile 16x32.
// NEW: manual register double-buffering of ldmatrix fragments (preload s+1
// before MMAs of s) to hide LDSM latency inside each warp — R10-13 showed
// tensor busy == HMMA floor (~97us) with ~170us of warp stalls insensitive
// to occupancy and LDS traffic => dependency-chain (short_scoreboard) bound.
// ============================================================================

#define N_  64
#define H_  112
#define W_  112
#define C_  64
#define HP  114
#define WP  114
#define M_CNT (N_*H_*W_)
#define NVEC  ((size_t)M_CNT * 16)
#define NPIX  (N_*H_*W_)
#define NTILES (NPIX/128)            // 6272
#define HW_   (H_*W_)                // 12544
#define PIXB  (C_*2)                 // 128 B per padded pixel
#define ROWB  (WP*PIXB)              // 14592 B per padded row
#define SBLK  1024                   // stats blocks

// B: [3 dy][192 k][64 co] fp16, 128B rows, XOR swizzle (k&7)<<4
#define BROWB  128
#define BCHUNKB (192*BROWB)          // 24576
#define B_BYTES (3*BCHUNKB)          // 73728

// A: per-PAIR [16 pixels][192 k] fp16, pitch 400B, double buffered
#define APITCH 400
#define AWBUF  (16*APITCH)           // 6400
#define SM_A0  B_BYTES
#define CONV_SMEM (B_BYTES + 8*2*AWBUF)   // 176128

// ---------------- persistent device scratch (zero-init .bss) ----------------
__device__ __align__(16) unsigned short g_xf[(size_t)N_ * HP * WP * C_];
__device__ __align__(16) unsigned short g_wb[3 * 192 * 64];
__device__ float g_psum[SBLK * C_];
__device__ float g_psq[SBLK * C_];
__device__ float g_scale[C_];
__device__ float g_shift[C_];
__device__ float g_bias[C_];
__device__ unsigned short g_bord[C_];

// ============================ PTX helpers ===================================
__device__ __forceinline__ uint32_t smem_to_u32(const void* p) {
    uint32_t a;
    asm("{ .reg .u64 t; cvta.to.shared.u64 t, %1; cvt.u32.u64 %0, t; }"
        : "=r"(a) : "l"(p));
    return a;
}

#define LDSM_X4(r, addr) \
    asm volatile("ldmatrix.sync.aligned.m8n8.x4.shared.b16 {%0,%1,%2,%3}, [%4];" \
        : "=r"((r)[0]), "=r"((r)[1]), "=r"((r)[2]), "=r"((r)[3]) : "r"(addr))

#define LDSM_X4_T(r, addr) \
    asm volatile("ldmatrix.sync.aligned.m8n8.x4.trans.shared.b16 {%0,%1,%2,%3}, [%4];" \
        : "=r"((r)[0]), "=r"((r)[1]), "=r"((r)[2]), "=r"((r)[3]) : "r"(addr))

#define MMA16816(c, a, b0v, b1v) \
    asm volatile("mma.sync.aligned.m16n8k16.row.col.f32.f16.f16.f32 " \
        "{%0,%1,%2,%3}, {%4,%5,%6,%7}, {%8,%9}, {%0,%1,%2,%3};" \
        : "+f"((c)[0]), "+f"((c)[1]), "+f"((c)[2]), "+f"((c)[3]) \
        : "r"((a)[0]), "r"((a)[1]), "r"((a)[2]), "r"((a)[3]), \
          "r"(b0v), "r"(b1v))

#define CP_ASYNC16(dst_s, src_g) \
    asm volatile("cp.async.cg.shared.global [%0], [%1], 16;" \
        :: "r"(dst_s), "l"(src_g))
#define CP_COMMIT() asm volatile("cp.async.commit_group;" ::: "memory")
#define CP_WAIT0()  asm volatile("cp.async.wait_group 0;" ::: "memory")
#define BAR_SYNC(id) asm volatile("bar.sync %0, 64;" :: "r"(id) : "memory")

__device__ __forceinline__ unsigned short f2h(float f) {
    __half h = __float2half_rn(f);
    return *reinterpret_cast<unsigned short*>(&h);
}

// ---------------------------------------------------------------------------
// Launch 0: per-channel partial moments (per-block) + raw-x fp16 conversion.
__global__ void __launch_bounds__(256) k_stats_conv(const float* __restrict__ x) {
    __shared__ float ssum[C_];
    __shared__ float ssq[C_];
    int tid = threadIdx.x;
    if (tid < C_) { ssum[tid] = 0.0f; ssq[tid] = 0.0f; }
    __syncthreads();

    const float4* xv = (const float4*)x;
    uint2* of = (uint2*)g_xf;
    int g = tid & 15;
    float4 s = make_float4(0.f, 0.f, 0.f, 0.f);
    float4 q = make_float4(0.f, 0.f, 0.f, 0.f);
    size_t stride = (size_t)gridDim.x * blockDim.x;
    for (size_t i = (size_t)blockIdx.x * blockDim.x + tid; i < NVEC; i += stride) {
        float4 v = xv[i];
        s.x += v.x; s.y += v.y; s.z += v.z; s.w += v.w;
        q.x += v.x * v.x; q.y += v.y * v.y; q.z += v.z * v.z; q.w += v.w * v.w;

        size_t pix = i >> 4;
        int n   = (int)(pix / HW_);
        int rem = (int)(pix % HW_);
        int h   = rem / W_;
        int w   = rem % W_;
        unsigned short h0 = f2h(v.x), h1 = f2h(v.y), h2 = f2h(v.z), h3 = f2h(v.w);
        size_t dpix = ((size_t)n * HP + (h + 1)) * WP + (w + 1);
        of[dpix * 16 + g] = make_uint2((uint32_t)h0 | ((uint32_t)h1 << 16),
                                       (uint32_t)h2 | ((uint32_t)h3 << 16));
    }
    atomicAdd(&ssum[g * 4 + 0], s.x); atomicAdd(&ssq[g * 4 + 0], q.x);
    atomicAdd(&ssum[g * 4 + 1], s.y); atomicAdd(&ssq[g * 4 + 1], q.y);
    atomicAdd(&ssum[g * 4 + 2], s.z); atomicAdd(&ssq[g * 4 + 2], q.z);
    atomicAdd(&ssum[g * 4 + 3], s.w); atomicAdd(&ssq[g * 4 + 3], q.w);
    __syncthreads();
    if (tid < C_) {
        g_psum[blockIdx.x * C_ + tid] = ssum[tid];
        g_psq [blockIdx.x * C_ + tid] = ssq[tid];
    }
}

// ---------------------------------------------------------------------------
// Launch 1: parallel reduce partials -> scale/shift/border + bias. 512 thr.
__global__ void __launch_bounds__(512) k_finprep(const float* __restrict__ beta,
                                                 const float* __restrict__ kw) {
    __shared__ float rs[C_ * 8];
    __shared__ float rq[C_ * 8];
    int tid = threadIdx.x;               // 512 = 64 channels x 8 slices
    int c = tid >> 3;
    int k = tid & 7;
    float s = 0.0f, q = 0.0f;
    for (int b = k; b < SBLK; b += 8) {
        s += g_psum[b * C_ + c];
        q += g_psq [b * C_ + c];
    }
    rs[tid] = s; rq[tid] = q;
    __syncthreads();
    if (tid < C_) {
        float ts = 0.0f, tq = 0.0f;
        #pragma unroll
        for (int i = 0; i < 8; i++) { ts += rs[tid * 8 + i]; tq += rq[tid * 8 + i]; }
        const float inv_m = 1.0f / (float)M_CNT;
        float m  = ts * inv_m;
        float v  = tq * inv_m - m * m;
        float sc = rsqrtf(v + 1e-5f);
        float sh = beta[tid] - m * sc;
        g_scale[tid] = sc;
        g_shift[tid] = sh;
        g_bord[tid]  = f2h(-sh / sc);
    }
    __syncthreads();
    {
        float acc = 0.0f;
        for (int t = k; t < 9; t += 8)
            for (int ci = 0; ci < 64; ci++)
                acc += kw[((size_t)t * 64 + ci) * 64 + c] * g_shift[ci];
        rs[tid] = acc;
    }
    __syncthreads();
    if (tid < C_) {
        float a = 0.0f;
        #pragma unroll
        for (int i = 0; i < 8; i++) a += rs[tid * 8 + i];
        g_bias[tid] = a;
    }
}

// ---------------------------------------------------------------------------
// Launch 2: swizzled B image + border fill.
__global__ void __launch_bounds__(256) k_bw(const float* __restrict__ kw) {
    int i = blockIdx.x * blockDim.x + threadIdx.x;
    if (i < 36864) {
        int cout = i & 63;
        int cin  = (i >> 6) & 63;
        int t    = i >> 12;            // dy*3+dx
        int dy = t / 3, dx = t % 3;
        float v = kw[((size_t)t * 64 + cin) * 64 + cout] * g_scale[cin];
        int kk = dx * 64 + cin;
        int off = kk * BROWB + cout * 2;
        off ^= (kk & 7) << 4;
        *(unsigned short*)((char*)g_wb + (size_t)dy * BCHUNKB + off) = f2h(v);
        return;
    }
    int idx = i - 36864;
    if (idx >= 64 * 452 * 16) return;
    int g   = idx & 15;
    int bp  = (idx >> 4) % 452;
    int img = (idx >> 4) / 452;
    int h, w;
    if (bp < 114)      { h = 0;   w = bp; }
    else if (bp < 228) { h = 113; w = bp - 114; }
    else { int j = bp - 228; h = 1 + (j >> 1); w = (j & 1) ? 113 : 0; }
    const unsigned short* bd = g_bord;
    uint32_t v0 = (uint32_t)bd[g*4+0] | ((uint32_t)bd[g*4+1] << 16);
    uint32_t v1 = (uint32_t)bd[g*4+2] | ((uint32_t)bd[g*4+3] << 16);
    ((uint2*)g_xf)[(((size_t)img * HP + h) * WP + w) * 16 + g] = make_uint2(v0, v1);
}

// ---------------------------------------------------------------------------
// Launch 3 (profiled): conv. 512 thr = 16 warps = 8 pairs; warp tile 16x32.
// Inner loop: manual register double-buffering (preload s+1 frags pre-MMA).
__global__ void __launch_bounds__(512, 1)
k_conv(float* __restrict__ out) {
    extern __shared__ __align__(1024) unsigned char smem[];
    uint32_t sb = smem_to_u32(smem);
    int tid = threadIdx.x;

    // stage B once (pre-swizzled image)
    {
        const uint4* src = (const uint4*)g_wb;
        uint4* dst = (uint4*)smem;
        for (int i = tid; i < B_BYTES / 16; i += 512) dst[i] = src[i];
    }
    __syncthreads();

    int lane = tid & 31;
    int wid  = tid >> 5;           // 0..15
    int pr   = wid >> 1;           // pair 0..7 -> pixels pr*16..+16
    int nw   = wid & 1;            // n-half: couts nw*32..+32
    int sel  = lane >> 3;
    int l7   = lane & 7;
    int barid = pr + 1;

    uint32_t apbase = sb + SM_A0 + (uint32_t)pr * (2 * AWBUF);
    uint32_t a_off  = (uint32_t)(((sel & 1) * 8 + l7) * APITCH + (sel >> 1) * 16);

    uint32_t b_lane = sb + (uint32_t)(((sel & 1) * 8 + l7) * BROWB);
    uint32_t bo0 = (uint32_t)((((sel >> 1) * 16) + nw * 64)      ^ (l7 << 4));
    uint32_t bo1 = (uint32_t)((((sel >> 1) * 16) + nw * 64 + 32) ^ (l7 << 4));

    // staging: 64 threads/pair; thread pt covers pixel pt>>2, quarter pt&3
    int pt = tid & 63;
    uint32_t dst_off = (uint32_t)((pt >> 2) * APITCH + (pt & 3) * 96);
    uint32_t src_off = (uint32_t)((pt & 3) * 96);
    const char* gx = (const char*)g_xf;

    int cq = lane & 3;
    float bia0[4], bia1[4];
    #pragma unroll
    for (int nf = 0; nf < 4; nf++) {
        bia0[nf] = g_bias[nw * 32 + nf * 8 + 2 * cq];
        bia1[nf] = g_bias[nw * 32 + nf * 8 + 2 * cq + 1];
    }

    uint32_t jj = 0;

    // prologue: prefetch (first tile, dy=0) into buf 0
    {
        int gp  = blockIdx.x * 128 + pr * 16 + (pt >> 2);
        int n   = gp / HW_;
        int rem = gp % HW_;
        int h   = rem / W_;
        int w   = rem % W_;
        const char* src = gx + (((size_t)n * HP + h) * WP + w) * PIXB + src_off;
        uint32_t d = apbase + dst_off;
        #pragma unroll
        for (int i = 0; i < 6; i++) CP_ASYNC16(d + i * 16, src + i * 16);
        CP_COMMIT();
    }

    for (int tile = blockIdx.x; tile < NTILES; tile += gridDim.x) {
        int gp  = tile * 128 + pr * 16 + (pt >> 2);
        int n   = gp / HW_;
        int rem = gp % HW_;
        int h   = rem / W_;
        int w   = rem % W_;
        const char* base = gx + (((size_t)n * HP + h) * WP + w) * PIXB + src_off;

        float c[16];
        #pragma unroll
        for (int i = 0; i < 16; i++) c[i] = 0.0f;

        #pragma unroll 1
        for (int j = 0; j < 3; j++) {
            uint32_t buf  = jj & 1;
            uint32_t nbuf = buf ^ 1;
            jj++;

            // 1) chunk data landed; 2) both warps of pair done reading nbuf
            CP_WAIT0();
            BAR_SYNC(barid);

            // 3) prefetch next chunk into nbuf (overlaps MMA loop below)
            if (j < 2) {
                const char* src = base + (size_t)(j + 1) * ROWB;
                uint32_t d = apbase + nbuf * AWBUF + dst_off;
                #pragma unroll
                for (int i = 0; i < 6; i++) CP_ASYNC16(d + i * 16, src + i * 16);
                CP_COMMIT();
            } else {
                int t2 = tile + gridDim.x;
                if (t2 < NTILES) {
                    int gp2  = t2 * 128 + pr * 16 + (pt >> 2);
                    int n2   = gp2 / HW_;
                    int rem2 = gp2 % HW_;
                    int h2   = rem2 / W_;
                    int w2   = rem2 % W_;
                    const char* src = gx + (((size_t)n2 * HP + h2) * WP + w2) * PIXB + src_off;
                    uint32_t d = apbase + nbuf * AWBUF + dst_off;
                    #pragma unroll
                    for (int i = 0; i < 6; i++) CP_ASYNC16(d + i * 16, src + i * 16);
                    CP_COMMIT();
                }
            }

            uint32_t Abase = apbase + buf * AWBUF + a_off;
            uint32_t Bbase = b_lane + (uint32_t)j * BCHUNKB;

            // -------- software-pipelined fragment loop (preload s+1) --------
            uint32_t ra[2][4], rb0[2][4], rb1[2][4];
            LDSM_X4(ra[0], Abase);
            LDSM_X4_T(rb0[0], Bbase + bo0);
            LDSM_X4_T(rb1[0], Bbase + bo1);

            #pragma unroll
            for (int s = 0; s < 12; s++) {
                int cur = s & 1;
                int nxt = cur ^ 1;
                if (s < 11) {
                    LDSM_X4(ra[nxt], Abase + (s + 1) * 32);
                    uint32_t Bs = Bbase + (uint32_t)(s + 1) * (16 * BROWB);
                    LDSM_X4_T(rb0[nxt], Bs + bo0);
                    LDSM_X4_T(rb1[nxt], Bs + bo1);
                }
                MMA16816(c +  0, ra[cur], rb0[cur][0], rb0[cur][1]);
                MMA16816(c +  4, ra[cur], rb0[cur][2], rb0[cur][3]);
                MMA16816(c +  8, ra[cur], rb1[cur][0], rb1[cur][1]);
                MMA16816(c + 12, ra[cur], rb1[cur][2], rb1[cur][3]);
            }
        }

        // epilogue: add bias, store 16 pixels x 32 couts
        int r = lane >> 2;
        int pix0 = tile * 128 + pr * 16 + r;
        float* o0 = out + (size_t)pix0 * 64 + nw * 32 + 2 * cq;
        float* o1 = o0 + 8 * 64;
        #pragma unroll
        for (int nf = 0; nf < 4; nf++) {
            *(float2*)(o0 + nf * 8) = make_float2(c[nf*4 + 0] + bia0[nf],
                                                  c[nf*4 + 1] + bia1[nf]);
            *(float2*)(o1 + nf * 8) = make_float2(c[nf*4 + 2] + bia0[nf],
                                                  c[nf*4 + 3] + bia1[nf]);
        }
    }
}

// ---------------------------------------------------------------------------
extern "C" void kernel_launch(void* const* d_in, const int* in_sizes, int n_in,
                              void* d_out, int out_size) {
    const float* x    = (const float*)d_in[0];
    const float* kw   = (const float*)d_in[1];
    const float* beta = (const float*)d_in[2];
    float* out = (float*)d_out;
    (void)in_sizes; (void)n_in; (void)out_size;

    cudaFuncSetAttribute(k_conv, cudaFuncAttributeMaxDynamicSharedMemorySize, CONV_SMEM);

    k_stats_conv<<<SBLK, 256>>>(x);                              // launch 0
    k_finprep<<<1, 512>>>(beta, kw);                             // launch 1
    k_bw<<<(36864 + 64 * 452 * 16 + 255) / 256, 256>>>(kw);      // launch 2
    k_conv<<<152, 512, CONV_SMEM>>>(out);                        // launch 3 (profiled)
}

// round 15
// speedup vs baseline: 1.2077x; 1.1724x over previous
#include <cuda_runtime.h>
#include <cuda_fp16.h>
#include <cstdint>

// ============================================================================
// x (64,112,112,64) f32 NHWC; kernels (3,3,64,64) f32 HWIO (+-1); beta (64).
// out = conv3x3_SAME(BN_train(x), kernels), fp32.
//
// BN folded into GEMM; padded border = fp16(-shift/scale). Implicit GEMM
// mma.sync.m16n8k16.f16. Conv: 512 thr = 8 pairs, warp tile 16x32.
// NEW (R15): per-tile ROW staging (3 padded rows x 18 px, 6.9KB/pair) instead
// of per-chunk im2col rows -> 3x less L2/cp.async traffic, ONE wait+bar per
// tile (was 3) so warps drift and LDSM overlaps MMA across warps. A-LDSM
// reads the swizzled row buffer directly (16 px groups never cross a row).
// ============================================================================

#define N_  64
#define H_  112
#define W_  112
#define C_  64
#define HP  114
#define WP  114
#define M_CNT (N_*H_*W_)
#define NVEC  ((size_t)M_CNT * 16)
#define NPIX  (N_*H_*W_)
#define NTILES (NPIX/128)            // 6272
#define HW_   (H_*W_)                // 12544
#define PIXB  (C_*2)                 // 128 B per padded pixel
#define SBLK  1024                   // stats blocks

// B: [3 dy][192 k][64 co] fp16, 128B rows, XOR swizzle (k&7)<<4
#define BROWB  128
#define BCHUNKB (192*BROWB)          // 24576
#define B_BYTES (3*BCHUNKB)          // 73728

// A: per-PAIR row window: 3 rows x 18 px x 128B, double buffered per tile
#define RBUF 2304                    // 18*128
#define PBUF (3*RBUF)                // 6912
#define SM_A0  B_BYTES
#define CONV_SMEM (B_BYTES + 8*2*PBUF)   // 184320

// ---------------- persistent device scratch (zero-init .bss) ----------------
__device__ __align__(16) unsigned short g_xf[(size_t)N_ * HP * WP * C_];
__device__ __align__(16) unsigned short g_wb[3 * 192 * 64];
__device__ float g_psum[SBLK * C_];
__device__ float g_psq[SBLK * C_];
__device__ float g_scale[C_];
__device__ float g_shift[C_];
__device__ float g_bias[C_];
__device__ unsigned short g_bord[C_];

// ============================ PTX helpers ===================================
__device__ __forceinline__ uint32_t smem_to_u32(const void* p) {
    uint32_t a;
    asm("{ .reg .u64 t; cvta.to.shared.u64 t, %1; cvt.u32.u64 %0, t; }"
        : "=r"(a) : "l"(p));
    return a;
}

#define LDSM_X4(r, addr) \
    asm volatile("ldmatrix.sync.aligned.m8n8.x4.shared.b16 {%0,%1,%2,%3}, [%4];" \
        : "=r"((r)[0]), "=r"((r)[1]), "=r"((r)[2]), "=r"((r)[3]) : "r"(addr))

#define LDSM_X4_T(r, addr) \
    asm volatile("ldmatrix.sync.aligned.m8n8.x4.trans.shared.b16 {%0,%1,%2,%3}, [%4];" \
        : "=r"((r)[0]), "=r"((r)[1]), "=r"((r)[2]), "=r"((r)[3]) : "r"(addr))

#define MMA16816(c, a, b0v, b1v) \
    asm volatile("mma.sync.aligned.m16n8k16.row.col.f32.f16.f16.f32 " \
        "{%0,%1,%2,%3}, {%4,%5,%6,%7}, {%8,%9}, {%0,%1,%2,%3};" \
        : "+f"((c)[0]), "+f"((c)[1]), "+f"((c)[2]), "+f"((c)[3]) \
        : "r"((a)[0]), "r"((a)[1]), "r"((a)[2]), "r"((a)[3]), \
          "r"(b0v), "r"(b1v))

#define CP_ASYNC16(dst_s, src_g) \
    asm volatile("cp.async.cg.shared.global [%0], [%1], 16;" \
        :: "r"(dst_s), "l"(src_g))
#define CP_COMMIT() asm volatile("cp.async.commit_group;" ::: "memory")
#define CP_WAIT0()  asm volatile("cp.async.wait_group 0;" ::: "memory")
#define BAR_SYNC(id) asm volatile("bar.sync %0, 64;" :: "r"(id) : "memory")

__device__ __forceinline__ unsigned short f2h(float f) {
    __half h = __float2half_rn(f);
    return *reinterpret_cast<unsigned short*>(&h);
}

// ---------------------------------------------------------------------------
// Launch 0: per-channel partial moments (per-block) + raw-x fp16 conversion.
__global__ void __launch_bounds__(256) k_stats_conv(const float* __restrict__ x) {
    __shared__ float ssum[C_];
    __shared__ float ssq[C_];
    int tid = threadIdx.x;
    if (tid < C_) { ssum[tid] = 0.0f; ssq[tid] = 0.0f; }
    __syncthreads();

    const float4* xv = (const float4*)x;
    uint2* of = (uint2*)g_xf;
    int g = tid & 15;
    float4 s = make_float4(0.f, 0.f, 0.f, 0.f);
    float4 q = make_float4(0.f, 0.f, 0.f, 0.f);
    size_t stride = (size_t)gridDim.x * blockDim.x;
    for (size_t i = (size_t)blockIdx.x * blockDim.x + tid; i < NVEC; i += stride) {
        float4 v = xv[i];
        s.x += v.x; s.y += v.y; s.z += v.z; s.w += v.w;
        q.x += v.x * v.x; q.y += v.y * v.y; q.z += v.z * v.z; q.w += v.w * v.w;

        size_t pix = i >> 4;
        int n   = (int)(pix / HW_);
        int rem = (int)(pix % HW_);
        int h   = rem / W_;
        int w   = rem % W_;
        unsigned short h0 = f2h(v.x), h1 = f2h(v.y), h2 = f2h(v.z), h3 = f2h(v.w);
        size_t dpix = ((size_t)n * HP + (h + 1)) * WP + (w + 1);
        of[dpix * 16 + g] = make_uint2((uint32_t)h0 | ((uint32_t)h1 << 16),
                                       (uint32_t)h2 | ((uint32_t)h3 << 16));
    }
    atomicAdd(&ssum[g * 4 + 0], s.x); atomicAdd(&ssq[g * 4 + 0], q.x);
    atomicAdd(&ssum[g * 4 + 1], s.y); atomicAdd(&ssq[g * 4 + 1], q.y);
    atomicAdd(&ssum[g * 4 + 2], s.z); atomicAdd(&ssq[g * 4 + 2], q.z);
    atomicAdd(&ssum[g * 4 + 3], s.w); atomicAdd(&ssq[g * 4 + 3], q.w);
    __syncthreads();
    if (tid < C_) {
        g_psum[blockIdx.x * C_ + tid] = ssum[tid];
        g_psq [blockIdx.x * C_ + tid] = ssq[tid];
    }
}

// ---------------------------------------------------------------------------
// Launch 1: parallel reduce partials -> scale/shift/border + bias. 512 thr.
__global__ void __launch_bounds__(512) k_finprep(const float* __restrict__ beta,
                                                 const float* __restrict__ kw) {
    __shared__ float rs[C_ * 8];
    __shared__ float rq[C_ * 8];
    int tid = threadIdx.x;
    int c = tid >> 3;
    int k = tid & 7;
    float s = 0.0f, q = 0.0f;
    for (int b = k; b < SBLK; b += 8) {
        s += g_psum[b * C_ + c];
        q += g_psq [b * C_ + c];
    }
    rs[tid] = s; rq[tid] = q;
    __syncthreads();
    if (tid < C_) {
        float ts = 0.0f, tq = 0.0f;
        #pragma unroll
        for (int i = 0; i < 8; i++) { ts += rs[tid * 8 + i]; tq += rq[tid * 8 + i]; }
        const float inv_m = 1.0f / (float)M_CNT;
        float m  = ts * inv_m;
        float v  = tq * inv_m - m * m;
        float sc = rsqrtf(v + 1e-5f);
        float sh = beta[tid] - m * sc;
        g_scale[tid] = sc;
        g_shift[tid] = sh;
        g_bord[tid]  = f2h(-sh / sc);
    }
    __syncthreads();
    {
        float acc = 0.0f;
        for (int t = k; t < 9; t += 8)
            for (int ci = 0; ci < 64; ci++)
                acc += kw[((size_t)t * 64 + ci) * 64 + c] * g_shift[ci];
        rs[tid] = acc;
    }
    __syncthreads();
    if (tid < C_) {
        float a = 0.0f;
        #pragma unroll
        for (int i = 0; i < 8; i++) a += rs[tid * 8 + i];
        g_bias[tid] = a;
    }
}

// ---------------------------------------------------------------------------
// Launch 2: swizzled B image + border fill.
__global__ void __launch_bounds__(256) k_bw(const float* __restrict__ kw) {
    int i = blockIdx.x * blockDim.x + threadIdx.x;
    if (i < 36864) {
        int cout = i & 63;
        int cin  = (i >> 6) & 63;
        int t    = i >> 12;            // dy*3+dx
        int dy = t / 3, dx = t % 3;
        float v = kw[((size_t)t * 64 + cin) * 64 + cout] * g_scale[cin];
        int kk = dx * 64 + cin;
        int off = kk * BROWB + cout * 2;
        off ^= (kk & 7) << 4;
        *(unsigned short*)((char*)g_wb + (size_t)dy * BCHUNKB + off) = f2h(v);
        return;
    }
    int idx = i - 36864;
    if (idx >= 64 * 452 * 16) return;
    int g   = idx & 15;
    int bp  = (idx >> 4) % 452;
    int img = (idx >> 4) / 452;
    int h, w;
    if (bp < 114)      { h = 0;   w = bp; }
    else if (bp < 228) { h = 113; w = bp - 114; }
    else { int j = bp - 228; h = 1 + (j >> 1); w = (j & 1) ? 113 : 0; }
    const unsigned short* bd = g_bord;
    uint32_t v0 = (uint32_t)bd[g*4+0] | ((uint32_t)bd[g*4+1] << 16);
    uint32_t v1 = (uint32_t)bd[g*4+2] | ((uint32_t)bd[g*4+3] << 16);
    ((uint2*)g_xf)[(((size_t)img * HP + h) * WP + w) * 16 + g] = make_uint2(v0, v1);
}

// ---------------------------------------------------------------------------
// Launch 3 (profiled): conv. 512 thr = 8 pairs; warp tile 16x32.
// Per-tile row staging: pair stages 3 padded rows x 18 px (swizzled),
// double buffered across TILES; one wait+bar per tile, no chunk-level sync.
__global__ void __launch_bounds__(512, 1)
k_conv(float* __restrict__ out) {
    extern __shared__ __align__(1024) unsigned char smem[];
    uint32_t sb = smem_to_u32(smem);
    int tid = threadIdx.x;

    // stage B once (pre-swizzled image)
    {
        const uint4* src = (const uint4*)g_wb;
        uint4* dst = (uint4*)smem;
        for (int i = tid; i < B_BYTES / 16; i += 512) dst[i] = src[i];
    }
    __syncthreads();

    int lane = tid & 31;
    int wid  = tid >> 5;           // 0..15
    int pr   = wid >> 1;           // pair 0..7 -> pixels pr*16..+16
    int nw   = wid & 1;            // n-half: couts nw*32..+32
    int sel  = lane >> 3;
    int l7   = lane & 7;
    int barid = pr + 1;

    uint32_t pairbuf = sb + SM_A0 + (uint32_t)pr * (2 * PBUF);

    // A lane addressing into row buffers: pixel-row p_row, per-dx base+mask
    int p_row = (sel & 1) * 8 + l7;                 // 0..15
    uint32_t abase[3], amask[3];
    #pragma unroll
    for (int dx = 0; dx < 3; dx++) {
        int qq = p_row + dx;                        // window col 0..17
        abase[dx] = (uint32_t)(qq * 128 + (sel >> 1) * 16);
        amask[dx] = (uint32_t)((qq & 7) << 4);
    }

    // B per-lane: row term + 2 swizzled cout-block byte offsets
    uint32_t b_lane = sb + (uint32_t)(((sel & 1) * 8 + l7) * BROWB);
    uint32_t bo0 = (uint32_t)((((sel >> 1) * 16) + nw * 64)      ^ (l7 << 4));
    uint32_t bo1 = (uint32_t)((((sel >> 1) * 16) + nw * 64 + 32) ^ (l7 << 4));

    // staging: 64 thr/pair; thread t<54 loads pixel-block (jrow, qcol) = 128B
    int pt   = tid & 63;
    int jrow = pt / 18;            // 0..2 (pt<54), else 3 (idle)
    int qcol = pt % 18;
    int svalid = pt < 54;
    uint32_t sdst = pairbuf;       // + buf*PBUF + jrow*RBUF + swz(qcol*128+i*16)
    uint32_t soff[8];
    #pragma unroll
    for (int i = 0; i < 8; i++)
        soff[i] = (uint32_t)(jrow * RBUF + ((qcol * 128 + i * 16) ^ ((qcol & 7) << 4)));
    const char* gx = (const char*)g_xf;

    int cq = lane & 3;
    float bia0[4], bia1[4];
    #pragma unroll
    for (int nf = 0; nf < 4; nf++) {
        bia0[nf] = g_bias[nw * 32 + nf * 8 + 2 * cq];
        bia1[nf] = g_bias[nw * 32 + nf * 8 + 2 * cq + 1];
    }

    // prologue: stage first tile into buf 0
    {
        int gp  = blockIdx.x * 128 + pr * 16;
        int n   = gp / HW_;
        int rem = gp % HW_;
        int h   = rem / W_;
        int w0  = rem % W_;
        if (svalid) {
            const char* src = gx + (((size_t)n * HP + h + jrow) * WP + w0 + qcol) * PIXB;
            #pragma unroll
            for (int i = 0; i < 8; i++) CP_ASYNC16(sdst + soff[i], src + i * 16);
        }
        CP_COMMIT();
    }

    uint32_t cur = 0;
    for (int tile = blockIdx.x; tile < NTILES; tile += gridDim.x) {
        // this tile's rows landed; both warps done with the other buffer
        CP_WAIT0();
        BAR_SYNC(barid);

        // prefetch next tile's rows into the other buffer (overlaps full MMA)
        int t2 = tile + gridDim.x;
        if (t2 < NTILES) {
            int gp2  = t2 * 128 + pr * 16;
            int n2   = gp2 / HW_;
            int rem2 = gp2 % HW_;
            int h2   = rem2 / W_;
            int w2   = rem2 % W_;
            if (svalid) {
                const char* src = gx + (((size_t)n2 * HP + h2 + jrow) * WP + w2 + qcol) * PIXB;
                uint32_t d = sdst + (cur ^ 1) * PBUF;
                #pragma unroll
                for (int i = 0; i < 8; i++) CP_ASYNC16(d + soff[i], src + i * 16);
            }
            CP_COMMIT();
        }

        float c[16];
        #pragma unroll
        for (int i = 0; i < 16; i++) c[i] = 0.0f;

        uint32_t tb = pairbuf + cur * PBUF;
        #pragma unroll
        for (int j = 0; j < 3; j++) {
            uint32_t Aj = tb + (uint32_t)j * RBUF;
            uint32_t Bbase = b_lane + (uint32_t)j * BCHUNKB;
            #pragma unroll
            for (int s = 0; s < 12; s++) {
                const int dx = s >> 2;
                uint32_t ra[4], rb0[4], rb1[4];
                LDSM_X4(ra, Aj + ((abase[dx] + (s & 3) * 32) ^ amask[dx]));
                uint32_t Bs = Bbase + (uint32_t)s * (16 * BROWB);
                LDSM_X4_T(rb0, Bs + bo0);
                LDSM_X4_T(rb1, Bs + bo1);

                MMA16816(c +  0, ra, rb0[0], rb0[1]);
                MMA16816(c +  4, ra, rb0[2], rb0[3]);
                MMA16816(c +  8, ra, rb1[0], rb1[1]);
                MMA16816(c + 12, ra, rb1[2], rb1[3]);
            }
        }
        cur ^= 1;

        // epilogue: add bias, store 16 pixels x 32 couts
        int r = lane >> 2;
        int pix0 = tile * 128 + pr * 16 + r;
        float* o0 = out + (size_t)pix0 * 64 + nw * 32 + 2 * cq;
        float* o1 = o0 + 8 * 64;
        #pragma unroll
        for (int nf = 0; nf < 4; nf++) {
            *(float2*)(o0 + nf * 8) = make_float2(c[nf*4 + 0] + bia0[nf],
                                                  c[nf*4 + 1] + bia1[nf]);
            *(float2*)(o1 + nf * 8) = make_float2(c[nf*4 + 2] + bia0[nf],
                                                  c[nf*4 + 3] + bia1[nf]);
        }
    }
}

// ---------------------------------------------------------------------------
extern "C" void kernel_launch(void* const* d_in, const int* in_sizes, int n_in,
                              void* d_out, int out_size) {
    const float* x    = (const float*)d_in[0];
    const float* kw   = (const float*)d_in[1];
    const float* beta = (const float*)d_in[2];
    float* out = (float*)d_out;
    (void)in_sizes; (void)n_in; (void)out_size;

    cudaFuncSetAttribute(k_conv, cudaFuncAttributeMaxDynamicSharedMemorySize, CONV_SMEM);

    k_stats_conv<<<SBLK, 256>>>(x);                              // launch 0
    k_finprep<<<1, 512>>>(beta, kw);                             // launch 1
    k_bw<<<(36864 + 64 * 452 * 16 + 255) / 256, 256>>>(kw);      // launch 2
    k_conv<<<152, 512, CONV_SMEM>>>(out);                        // launch 3 (profiled)
}

// round 16
// speedup vs baseline: 1.3703x; 1.1347x over previous
#include <cuda_runtime.h>
#include <cuda_fp16.h>
#include <cstdint>

// ============================================================================
// x (64,112,112,64) f32 NHWC; kernels (3,3,64,64) f32 HWIO (+-1); beta (64).
// out = conv3x3_SAME(BN_train(x), kernels), fp32.
//
// BN folded into GEMM; padded border = fp16(-shift/scale). Implicit GEMM
// mma.sync.m16n8k16.f16. Conv: 512 thr = 8 pairs; warp tile 32x32 over a
// pair-owned DUAL 16-px row-window (two windows of 3 rows x 18 px). Row
// buffer j is only read during chunk j -> recycled per-chunk for the next
// tile (wait_group 2 + pair bar), keeping staging/compute overlap with
// single-buffer smem. LDS bytes/MAC 0.1875 -> 0.125 (R15: L1=81% wall).
// ============================================================================

#define N_  64
#define H_  112
#define W_  112
#define C_  64
#define HP  114
#define WP  114
#define M_CNT (N_*H_*W_)
#define NVEC  ((size_t)M_CNT * 16)
#define NPIX  (N_*H_*W_)
#define HW_   (H_*W_)                // 12544
#define PIXB  (C_*2)                 // 128 B per padded pixel
#define SBLK  1024                   // stats blocks

#define CTATILE 256
#define NT3   (NPIX/CTATILE)         // 3136 exact

// B: [3 dy][192 k][64 co] fp16, 128B rows, XOR swizzle (k&7)<<4
#define BROWB  128
#define BCHUNKB (192*BROWB)          // 24576
#define B_BYTES (3*BCHUNKB)          // 73728

// A: per-PAIR dual window: 2 x (3 rows x 18 px x 128B), single buffer
#define RBUF 2304                    // 18*128
#define WINB (3*RBUF)                // 6912
#define PRBUF (2*WINB)               // 13824
#define SM_A0  B_BYTES
#define CONV_SMEM (B_BYTES + 8*PRBUF)   // 184320

// ---------------- persistent device scratch (zero-init .bss) ----------------
__device__ __align__(16) unsigned short g_xf[(size_t)N_ * HP * WP * C_];
__device__ __align__(16) unsigned short g_wb[3 * 192 * 64];
__device__ float g_psum[SBLK * C_];
__device__ float g_psq[SBLK * C_];
__device__ float g_scale[C_];
__device__ float g_shift[C_];
__device__ float g_bias[C_];
__device__ unsigned short g_bord[C_];

// ============================ PTX helpers ===================================
__device__ __forceinline__ uint32_t smem_to_u32(const void* p) {
    uint32_t a;
    asm("{ .reg .u64 t; cvta.to.shared.u64 t, %1; cvt.u32.u64 %0, t; }"
        : "=r"(a) : "l"(p));
    return a;
}

#define LDSM_X4(r, addr) \
    asm volatile("ldmatrix.sync.aligned.m8n8.x4.shared.b16 {%0,%1,%2,%3}, [%4];" \
        : "=r"((r)[0]), "=r"((r)[1]), "=r"((r)[2]), "=r"((r)[3]) : "r"(addr))

#define LDSM_X4_T(r, addr) \
    asm volatile("ldmatrix.sync.aligned.m8n8.x4.trans.shared.b16 {%0,%1,%2,%3}, [%4];" \
        : "=r"((r)[0]), "=r"((r)[1]), "=r"((r)[2]), "=r"((r)[3]) : "r"(addr))

#define MMA16816(c, a, b0v, b1v) \
    asm volatile("mma.sync.aligned.m16n8k16.row.col.f32.f16.f16.f32 " \
        "{%0,%1,%2,%3}, {%4,%5,%6,%7}, {%8,%9}, {%0,%1,%2,%3};" \
        : "+f"((c)[0]), "+f"((c)[1]), "+f"((c)[2]), "+f"((c)[3]) \
        : "r"((a)[0]), "r"((a)[1]), "r"((a)[2]), "r"((a)[3]), \
          "r"(b0v), "r"(b1v))

#define CP_ASYNC16(dst_s, src_g) \
    asm volatile("cp.async.cg.shared.global [%0], [%1], 16;" \
        :: "r"(dst_s), "l"(src_g))
#define CP_COMMIT() asm volatile("cp.async.commit_group;" ::: "memory")
#define CP_WAIT2()  asm volatile("cp.async.wait_group 2;" ::: "memory")
#define BAR_SYNC(id) asm volatile("bar.sync %0, 64;" :: "r"(id) : "memory")

__device__ __forceinline__ unsigned short f2h(float f) {
    __half h = __float2half_rn(f);
    return *reinterpret_cast<unsigned short*>(&h);
}

// ---------------------------------------------------------------------------
// Launch 0: per-channel partial moments (per-block) + raw-x fp16 conversion.
__global__ void __launch_bounds__(256) k_stats_conv(const float* __restrict__ x) {
    __shared__ float ssum[C_];
    __shared__ float ssq[C_];
    int tid = threadIdx.x;
    if (tid < C_) { ssum[tid] = 0.0f; ssq[tid] = 0.0f; }
    __syncthreads();

    const float4* xv = (const float4*)x;
    uint2* of = (uint2*)g_xf;
    int g = tid & 15;
    float4 s = make_float4(0.f, 0.f, 0.f, 0.f);
    float4 q = make_float4(0.f, 0.f, 0.f, 0.f);
    size_t stride = (size_t)gridDim.x * blockDim.x;
    for (size_t i = (size_t)blockIdx.x * blockDim.x + tid; i < NVEC; i += stride) {
        float4 v = xv[i];
        s.x += v.x; s.y += v.y; s.z += v.z; s.w += v.w;
        q.x += v.x * v.x; q.y += v.y * v.y; q.z += v.z * v.z; q.w += v.w * v.w;

        size_t pix = i >> 4;
        int n   = (int)(pix / HW_);
        int rem = (int)(pix % HW_);
        int h   = rem / W_;
        int w   = rem % W_;
        unsigned short h0 = f2h(v.x), h1 = f2h(v.y), h2 = f2h(v.z), h3 = f2h(v.w);
        size_t dpix = ((size_t)n * HP + (h + 1)) * WP + (w + 1);
        of[dpix * 16 + g] = make_uint2((uint32_t)h0 | ((uint32_t)h1 << 16),
                                       (uint32_t)h2 | ((uint32_t)h3 << 16));
    }
    atomicAdd(&ssum[g * 4 + 0], s.x); atomicAdd(&ssq[g * 4 + 0], q.x);
    atomicAdd(&ssum[g * 4 + 1], s.y); atomicAdd(&ssq[g * 4 + 1], q.y);
    atomicAdd(&ssum[g * 4 + 2], s.z); atomicAdd(&ssq[g * 4 + 2], q.z);
    atomicAdd(&ssum[g * 4 + 3], s.w); atomicAdd(&ssq[g * 4 + 3], q.w);
    __syncthreads();
    if (tid < C_) {
        g_psum[blockIdx.x * C_ + tid] = ssum[tid];
        g_psq [blockIdx.x * C_ + tid] = ssq[tid];
    }
}

// ---------------------------------------------------------------------------
// Launch 1: parallel reduce partials -> scale/shift/border + bias. 512 thr.
__global__ void __launch_bounds__(512) k_finprep(const float* __restrict__ beta,
                                                 const float* __restrict__ kw) {
    __shared__ float rs[C_ * 8];
    __shared__ float rq[C_ * 8];
    int tid = threadIdx.x;
    int c = tid >> 3;
    int k = tid & 7;
    float s = 0.0f, q = 0.0f;
    for (int b = k; b < SBLK; b += 8) {
        s += g_psum[b * C_ + c];
        q += g_psq [b * C_ + c];
    }
    rs[tid] = s; rq[tid] = q;
    __syncthreads();
    if (tid < C_) {
        float ts = 0.0f, tq = 0.0f;
        #pragma unroll
        for (int i = 0; i < 8; i++) { ts += rs[tid * 8 + i]; tq += rq[tid * 8 + i]; }
        const float inv_m = 1.0f / (float)M_CNT;
        float m  = ts * inv_m;
        float v  = tq * inv_m - m * m;
        float sc = rsqrtf(v + 1e-5f);
        float sh = beta[tid] - m * sc;
        g_scale[tid] = sc;
        g_shift[tid] = sh;
        g_bord[tid]  = f2h(-sh / sc);
    }
    __syncthreads();
    {
        float acc = 0.0f;
        for (int t = k; t < 9; t += 8)
            for (int ci = 0; ci < 64; ci++)
                acc += kw[((size_t)t * 64 + ci) * 64 + c] * g_shift[ci];
        rs[tid] = acc;
    }
    __syncthreads();
    if (tid < C_) {
        float a = 0.0f;
        #pragma unroll
        for (int i = 0; i < 8; i++) a += rs[tid * 8 + i];
        g_bias[tid] = a;
    }
}

// ---------------------------------------------------------------------------
// Launch 2: swizzled B image + border fill.
__global__ void __launch_bounds__(256) k_bw(const float* __restrict__ kw) {
    int i = blockIdx.x * blockDim.x + threadIdx.x;
    if (i < 36864) {
        int cout = i & 63;
        int cin  = (i >> 6) & 63;
        int t    = i >> 12;            // dy*3+dx
        int dy = t / 3, dx = t % 3;
        float v = kw[((size_t)t * 64 + cin) * 64 + cout] * g_scale[cin];
        int kk = dx * 64 + cin;
        int off = kk * BROWB + cout * 2;
        off ^= (kk & 7) << 4;
        *(unsigned short*)((char*)g_wb + (size_t)dy * BCHUNKB + off) = f2h(v);
        return;
    }
    int idx = i - 36864;
    if (idx >= 64 * 452 * 16) return;
    int g   = idx & 15;
    int bp  = (idx >> 4) % 452;
    int img = (idx >> 4) / 452;
    int h, w;
    if (bp < 114)      { h = 0;   w = bp; }
    else if (bp < 228) { h = 113; w = bp - 114; }
    else { int j = bp - 228; h = 1 + (j >> 1); w = (j & 1) ? 113 : 0; }
    const unsigned short* bd = g_bord;
    uint32_t v0 = (uint32_t)bd[g*4+0] | ((uint32_t)bd[g*4+1] << 16);
    uint32_t v1 = (uint32_t)bd[g*4+2] | ((uint32_t)bd[g*4+3] << 16);
    ((uint2*)g_xf)[(((size_t)img * HP + h) * WP + w) * 16 + g] = make_uint2(v0, v1);
}

// ---------------------------------------------------------------------------
// Launch 3 (profiled): conv. 512 thr = 8 pairs; warp tile 32x32 (dual window).
// Row buffer j recycled per chunk: wait_group(2) -> bar -> MMA(j) -> bar ->
// issue row j of next tile -> commit. 3 groups in flight per thread.
__global__ void __launch_bounds__(512, 1)
k_conv(float* __restrict__ out) {
    extern __shared__ __align__(1024) unsigned char smem[];
    uint32_t sb = smem_to_u32(smem);
    int tid = threadIdx.x;

    // stage B once (pre-swizzled image)
    {
        const uint4* src = (const uint4*)g_wb;
        uint4* dst = (uint4*)smem;
        for (int i = tid; i < B_BYTES / 16; i += 512) dst[i] = src[i];
    }
    __syncthreads();

    int lane = tid & 31;
    int wid  = tid >> 5;           // 0..15
    int pr   = wid >> 1;           // pair 0..7 -> pixel groups 2pr, 2pr+1
    int nw   = wid & 1;            // n-half: couts nw*32..+32
    int sel  = lane >> 3;
    int l7   = lane & 7;
    int barid = pr + 1;

    uint32_t pairbuf = sb + SM_A0 + (uint32_t)pr * PRBUF;

    // A lane addressing (per dx) — same for both windows, different base
    int p_row = (sel & 1) * 8 + l7;                 // 0..15
    uint32_t abase[3], amask[3];
    #pragma unroll
    for (int dx = 0; dx < 3; dx++) {
        int qq = p_row + dx;                        // window col 0..17
        abase[dx] = (uint32_t)(qq * 128 + (sel >> 1) * 16);
        amask[dx] = (uint32_t)((qq & 7) << 4);
    }

    // B per-lane: row term + 2 swizzled cout-block byte offsets (nw half)
    uint32_t b_lane = sb + (uint32_t)(((sel & 1) * 8 + l7) * BROWB);
    uint32_t bo0 = (uint32_t)((((sel >> 1) * 16) + nw * 64)      ^ (l7 << 4));
    uint32_t bo1 = (uint32_t)((((sel >> 1) * 16) + nw * 64 + 32) ^ (l7 << 4));

    // staging: 64 thr/pair; threads pt<36 stage one row of one window:
    // swin = pt/18 (window 0/1), qcol = pt%18; 8 x cp.async (128 B block).
    int pt    = tid & 63;
    int swin  = pt / 18;
    int qcol  = pt % 18;
    int svalid = pt < 36;
    uint32_t sdst = pairbuf + (uint32_t)swin * WINB;   // + j*RBUF + soff[i]
    uint32_t soff[8];
    #pragma unroll
    for (int i = 0; i < 8; i++)
        soff[i] = (uint32_t)((qcol * 128 + i * 16) ^ ((qcol & 7) << 4));
    const char* gx = (const char*)g_xf;

    int cq = lane & 3;
    float bia0[4], bia1[4];
    #pragma unroll
    for (int nf = 0; nf < 4; nf++) {
        bia0[nf] = g_bias[nw * 32 + nf * 8 + 2 * cq];
        bia1[nf] = g_bias[nw * 32 + nf * 8 + 2 * cq + 1];
    }

    // my staging window coords for a given tile
    // gp = tile*256 + (2pr+swin)*16  ->  (n, h, w0); 16 | 112 so no row cross
    // prologue: stage all 3 rows of first tile (3 commits)
    {
        int gp  = blockIdx.x * CTATILE + (2 * pr + swin) * 16;
        int n   = gp / HW_;
        int rem = gp % HW_;
        int h   = rem / W_;
        int w0  = rem % W_;
        const char* srow = gx + (((size_t)n * HP + h) * WP + w0 + qcol) * PIXB;
        #pragma unroll
        for (int j = 0; j < 3; j++) {
            if (svalid) {
                const char* src = srow + (size_t)j * (WP * PIXB);
                uint32_t d = sdst + (uint32_t)j * RBUF;
                #pragma unroll
                for (int i = 0; i < 8; i++) CP_ASYNC16(d + soff[i], src + i * 16);
            }
            CP_COMMIT();
        }
    }

    for (int tile = blockIdx.x; tile < NT3; tile += gridDim.x) {
        // next tile's staging source (uniform per staging thread)
        int t2 = tile + gridDim.x;
        const char* srow2 = nullptr;
        if (t2 < NT3) {
            int gp2  = t2 * CTATILE + (2 * pr + swin) * 16;
            int n2   = gp2 / HW_;
            int rem2 = gp2 % HW_;
            int h2   = rem2 / W_;
            int w2   = rem2 % W_;
            srow2 = gx + (((size_t)n2 * HP + h2) * WP + w2 + qcol) * PIXB;
        }

        float c[32];
        #pragma unroll
        for (int i = 0; i < 32; i++) c[i] = 0.0f;

        #pragma unroll
        for (int j = 0; j < 3; j++) {
            // row j of this tile landed (own groups), both warps see it
            CP_WAIT2();
            BAR_SYNC(barid);

            uint32_t Aj0 = pairbuf + (uint32_t)j * RBUF;
            uint32_t Aj1 = Aj0 + WINB;
            uint32_t Bbase = b_lane + (uint32_t)j * BCHUNKB;

            #pragma unroll
            for (int s = 0; s < 12; s++) {
                const int dx = s >> 2;
                uint32_t aoff = (abase[dx] + (s & 3) * 32) ^ amask[dx];
                uint32_t ra0[4], ra1[4], rb0[4], rb1[4];
                LDSM_X4(ra0, Aj0 + aoff);
                LDSM_X4(ra1, Aj1 + aoff);
                uint32_t Bs = Bbase + (uint32_t)s * (16 * BROWB);
                LDSM_X4_T(rb0, Bs + bo0);
                LDSM_X4_T(rb1, Bs + bo1);

                MMA16816(c +  0, ra0, rb0[0], rb0[1]);
                MMA16816(c +  4, ra0, rb0[2], rb0[3]);
                MMA16816(c +  8, ra0, rb1[0], rb1[1]);
                MMA16816(c + 12, ra0, rb1[2], rb1[3]);
                MMA16816(c + 16, ra1, rb0[0], rb0[1]);
                MMA16816(c + 20, ra1, rb0[2], rb0[3]);
                MMA16816(c + 24, ra1, rb1[0], rb1[1]);
                MMA16816(c + 28, ra1, rb1[2], rb1[3]);
            }

            // both warps finished reading row j -> recycle it for next tile
            BAR_SYNC(barid);
            if (srow2 && svalid) {
                const char* src = srow2 + (size_t)j * (WP * PIXB);
                uint32_t d = sdst + (uint32_t)j * RBUF;
                #pragma unroll
                for (int i = 0; i < 8; i++) CP_ASYNC16(d + soff[i], src + i * 16);
            }
            CP_COMMIT();
        }

        // epilogue: add bias, store 2 x 16 pixels x 32 couts
        int r = lane >> 2;
        #pragma unroll
        for (int mf = 0; mf < 2; mf++) {
            int pix0 = tile * CTATILE + (2 * pr + mf) * 16 + r;
            float* p0 = out + (size_t)pix0 * 64 + nw * 32 + 2 * cq;
            float* p1 = p0 + 8 * 64;
            #pragma unroll
            for (int nf = 0; nf < 4; nf++) {
                *(float2*)(p0 + nf * 8) = make_float2(c[mf*16 + nf*4 + 0] + bia0[nf],
                                                      c[mf*16 + nf*4 + 1] + bia1[nf]);
                *(float2*)(p1 + nf * 8) = make_float2(c[mf*16 + nf*4 + 2] + bia0[nf],
                                                      c[mf*16 + nf*4 + 3] + bia1[nf]);
            }
        }
    }
}

// ---------------------------------------------------------------------------
extern "C" void kernel_launch(void* const* d_in, const int* in_sizes, int n_in,
                              void* d_out, int out_size) {
    const float* x    = (const float*)d_in[0];
    const float* kw   = (const float*)d_in[1];
    const float* beta = (const float*)d_in[2];
    float* out = (float*)d_out;
    (void)in_sizes; (void)n_in; (void)out_size;

    cudaFuncSetAttribute(k_conv, cudaFuncAttributeMaxDynamicSharedMemorySize, CONV_SMEM);

    k_stats_conv<<<SBLK, 256>>>(x);                              // launch 0
    k_finprep<<<1, 512>>>(beta, kw);                             // launch 1
    k_bw<<<(36864 + 64 * 452 * 16 + 255) / 256, 256>>>(kw);      // launch 2
    k_conv<<<152, 512, CONV_SMEM>>>(out);                        // launch 3 (profiled)
}